// round 5
// baseline (speedup 1.0000x reference)
#include <cuda_runtime.h>

// ---------------------------------------------------------------------------
// TreeConvLSTM3d: 3D U-Net encoder -> conv TreeLSTM over 31-node binary tree
// -> 3D U-Net decoder with skip connections. All fp32 direct convolutions.
// ---------------------------------------------------------------------------

#define NB 31

// Scratch arena (float count), with buffer-lifetime reuse (~392 MB).
__device__ float g_arena[98000000];

__device__ __forceinline__ float sigm(float x){ return 1.f/(1.f + expf(-x)); }

// Generic 3x3x3 conv, pad=1, NCDHW / OIDHW (cross-correlation like lax.conv).
// Each thread computes a 4-wide x strip for COTILE consecutive output channels.
// grid = (D, COUT/COTILE, NBATCH), block = (D/4, D, 1).
template<int COTILE>
__global__ void conv3_k(const float* __restrict__ in, const float* __restrict__ w,
                        const float* __restrict__ bias, float* __restrict__ out,
                        int CIN, int COUT, int D, int doRelu)
{
    extern __shared__ float ws[];
    const int n   = blockIdx.z;
    const int co0 = blockIdx.y * COTILE;
    const int z   = blockIdx.x;
    const int tid = threadIdx.y * blockDim.x + threadIdx.x;
    const int nt  = blockDim.x * blockDim.y;
    const int wcount = COTILE * CIN * 27;
    const float* wsrc = w + (size_t)co0 * CIN * 27;
    for (int i = tid; i < wcount; i += nt) ws[i] = wsrc[i];
    __syncthreads();

    const int y  = threadIdx.y;
    const int x0 = threadIdx.x * 4;
    const int DD = D * D;
    const size_t DDD = (size_t)DD * D;

    float acc[COTILE][4];
    #pragma unroll
    for (int t = 0; t < COTILE; t++){
        float bv = bias ? __ldg(bias + co0 + t) : 0.f;
        #pragma unroll
        for (int v = 0; v < 4; v++) acc[t][v] = bv;
    }

    for (int ci = 0; ci < CIN; ci++){
        const float* ipbase = in + ((size_t)n * CIN + ci) * DDD;
        const float* wci = ws + ci * 27;
        #pragma unroll
        for (int dz = 0; dz < 3; dz++){
            int zz = z + dz - 1;
            if ((unsigned)zz >= (unsigned)D) continue;      // uniform over block
            #pragma unroll
            for (int dy = 0; dy < 3; dy++){
                int yy = y + dy - 1;
                bool yok = (unsigned)yy < (unsigned)D;
                const float* ip = ipbase + (size_t)zz * DD + yy * D;
                float r[6];
                #pragma unroll
                for (int j = 0; j < 6; j++){
                    int xx = x0 - 1 + j;
                    r[j] = (yok && (unsigned)xx < (unsigned)D) ? __ldg(ip + xx) : 0.f;
                }
                const int tap0 = dz * 9 + dy * 3;
                #pragma unroll
                for (int dx = 0; dx < 3; dx++){
                    #pragma unroll
                    for (int t = 0; t < COTILE; t++){
                        float wv = wci[t * CIN * 27 + tap0 + dx];
                        #pragma unroll
                        for (int v = 0; v < 4; v++)
                            acc[t][v] += r[dx + v] * wv;
                    }
                }
            }
        }
    }

    #pragma unroll
    for (int t = 0; t < COTILE; t++){
        float* op = out + ((size_t)n * COUT + co0 + t) * DDD + (size_t)z * DD + y * D + x0;
        #pragma unroll
        for (int v = 0; v < 4; v++){
            float r = acc[t][v];
            if (doRelu) r = fmaxf(r, 0.f);
            op[v] = r;
        }
    }
}

// 2x2x2 maxpool, stride 2.
__global__ void pool_k(const float* __restrict__ in, float* __restrict__ out,
                       int C, int Dout, int total)
{
    int idx = blockIdx.x * blockDim.x + threadIdx.x;
    if (idx >= total) return;
    int x = idx % Dout; int t = idx / Dout;
    int y = t % Dout; t /= Dout;
    int z = t % Dout; t /= Dout;
    int c = t % C; int n = t / C;
    int Din = Dout * 2;
    const float* p = in + ((((size_t)n * C + c) * Din + 2 * z) * Din + 2 * y) * Din + 2 * x;
    float m = fmaxf(fmaxf(p[0], p[1]), fmaxf(p[Din], p[Din + 1]));
    const float* q = p + (size_t)Din * Din;
    m = fmaxf(m, fmaxf(fmaxf(q[0], q[1]), fmaxf(q[Din], q[Din + 1])));
    out[idx] = m;
}

// Leaf nodes 15..30: iou = Wx, c_in = c0.
__global__ void leaf_k(const float* __restrict__ wx, const float* __restrict__ biou,
                       const float* __restrict__ c0, float* __restrict__ h, float* __restrict__ c)
{
    int idx = blockIdx.x * blockDim.x + threadIdx.x;
    if (idx >= 16 * 10 * 512) return;
    int vox = idx & 511;
    int ch  = (idx >> 9) % 10;
    int node = 15 + idx / 5120;
    float i = wx[((size_t)node * 30 + ch) * 512 + vox]      + biou[ch * 512 + vox];
    float o = wx[((size_t)node * 30 + 10 + ch) * 512 + vox] + biou[(10 + ch) * 512 + vox];
    float u = wx[((size_t)node * 30 + 20 + ch) * 512 + vox] + biou[(20 + ch) * 512 + vox];
    float cc = sigm(i) * tanhf(u) + c0[((size_t)node * 10 + ch) * 512 + vox];
    float hh = sigm(o) * tanhf(cc);
    h[((size_t)node * 10 + ch) * 512 + vox] = hh;
    c[((size_t)node * 10 + ch) * 512 + vox] = cc;
}

// h_sum over child pairs for a level: children of level are contiguous nodes.
__global__ void hsum_k(const float* __restrict__ h, float* __restrict__ hs, int cbase, int P)
{
    int idx = blockIdx.x * blockDim.x + threadIdx.x;
    if (idx >= P * 5120) return;
    int p = idx / 5120, r = idx % 5120;
    hs[idx] = h[(size_t)(cbase + 2 * p) * 5120 + r] + h[(size_t)(cbase + 2 * p + 1) * 5120 + r];
}

// Internal-node update: gates from iou conv, forget from per-child f conv.
__global__ void node_k(const float* __restrict__ iou, const float* __restrict__ fraw,
                       const float* __restrict__ biou,
                       float* __restrict__ h, float* __restrict__ c,
                       int base, int P, int cbase)
{
    int idx = blockIdx.x * blockDim.x + threadIdx.x;
    if (idx >= P * 5120) return;
    int vox = idx & 511;
    int ch  = (idx >> 9) % 10;
    int p   = idx / 5120;
    float i = iou[((size_t)p * 30 + ch) * 512 + vox]      + biou[ch * 512 + vox];
    float o = iou[((size_t)p * 30 + 10 + ch) * 512 + vox] + biou[(10 + ch) * 512 + vox];
    float u = iou[((size_t)p * 30 + 20 + ch) * 512 + vox] + biou[(20 + ch) * 512 + vox];
    float f0 = sigm(fraw[((size_t)(2 * p) * 10 + ch) * 512 + vox]);
    float f1 = sigm(fraw[((size_t)(2 * p + 1) * 10 + ch) * 512 + vox]);
    float cred = f0 * c[((size_t)(cbase + 2 * p) * 10 + ch) * 512 + vox]
               + f1 * c[((size_t)(cbase + 2 * p + 1) * 10 + ch) * 512 + vox];
    float cc = sigm(i) * tanhf(u) + cred;
    float hh = sigm(o) * tanhf(cc);
    h[((size_t)(base + p) * 10 + ch) * 512 + vox] = hh;
    c[((size_t)(base + p) * 10 + ch) * 512 + vox] = cc;
}

// concat(up2(h_all)[10ch], x1[20ch]) at 16^3.
__global__ void cat2_k(const float* __restrict__ h, const float* __restrict__ x1,
                       float* __restrict__ out)
{
    int idx = blockIdx.x * blockDim.x + threadIdx.x;
    if (idx >= NB * 30 * 4096) return;
    int vox = idx % 4096;
    int cch = (idx / 4096) % 30;
    int n   = idx / (30 * 4096);
    float v;
    if (cch < 10){
        int x = vox & 15, y = (vox >> 4) & 15, z = vox >> 8;
        v = h[((size_t)n * 10 + cch) * 512 + ((size_t)(z >> 1) * 8 + (y >> 1)) * 8 + (x >> 1)];
    } else {
        v = x1[((size_t)n * 20 + (cch - 10)) * 4096 + vox];
    }
    out[idx] = v;
}

// concat(up2(d2b)[32ch], x0[16ch]) at 32^3.
__global__ void cat1_k(const float* __restrict__ d2b, const float* __restrict__ x0,
                       float* __restrict__ out)
{
    size_t idx = (size_t)blockIdx.x * blockDim.x + threadIdx.x;
    if (idx >= (size_t)NB * 48 * 32768) return;
    int vox = (int)(idx & 32767);
    int cch = (int)((idx >> 15) % 48);
    int n   = (int)(idx / ((size_t)48 * 32768));
    float v;
    if (cch < 32){
        int x = vox & 31, y = (vox >> 5) & 31, z = vox >> 10;
        v = d2b[((size_t)n * 32 + cch) * 4096 + ((size_t)(z >> 1) * 16 + (y >> 1)) * 16 + (x >> 1)];
    } else {
        v = x0[((size_t)n * 16 + (cch - 32)) * 32768 + vox];
    }
    out[idx] = v;
}

// Final 1x1x1 conv: 16 -> 1.
__global__ void d1c_k(const float* __restrict__ in, const float* __restrict__ w,
                      const float* __restrict__ b, float* __restrict__ out)
{
    int idx = blockIdx.x * blockDim.x + threadIdx.x;
    if (idx >= NB * 32768) return;
    int n = idx >> 15;
    int vox = idx & 32767;
    float acc = __ldg(b);
    #pragma unroll
    for (int ci = 0; ci < 16; ci++)
        acc += in[((size_t)n * 16 + ci) * 32768 + vox] * __ldg(w + ci);
    out[idx] = acc;
}

extern "C" void kernel_launch(void* const* d_in, const int* in_sizes, int n_in,
                              void* d_out, int out_size)
{
    const float* data  = (const float*)d_in[0];
    // d_in[1] = h0 (unused: every node's h is overwritten)
    const float* c0    = (const float*)d_in[2];
    const float* e1a_w = (const float*)d_in[3];  const float* e1a_b = (const float*)d_in[4];
    const float* e1b_w = (const float*)d_in[5];  const float* e1b_b = (const float*)d_in[6];
    const float* e2a_w = (const float*)d_in[7];  const float* e2a_b = (const float*)d_in[8];
    const float* e2b_w = (const float*)d_in[9];  const float* e2b_b = (const float*)d_in[10];
    const float* d2a_w = (const float*)d_in[11]; const float* d2a_b = (const float*)d_in[12];
    const float* d2b_w = (const float*)d_in[13]; const float* d2b_b = (const float*)d_in[14];
    const float* d1a_w = (const float*)d_in[15]; const float* d1a_b = (const float*)d_in[16];
    const float* d1b_w = (const float*)d_in[17]; const float* d1b_b = (const float*)d_in[18];
    const float* d1c_w = (const float*)d_in[19]; const float* d1c_b = (const float*)d_in[20];
    const float* w_iou = (const float*)d_in[21];
    const float* u_iou = (const float*)d_in[22];
    const float* u_f   = (const float*)d_in[23];
    const float* b_iou = (const float*)d_in[24];
    float* out = (float*)d_out;

    float* A = nullptr;
    cudaGetSymbolAddress((void**)&A, g_arena);

    // Buffer-lifetime-overlapped arena layout.
    size_t o = 0;
    float* g_t1  = A + o; o += (size_t)NB * 16 * 32768;   // e1a out; later reused as d1a out
    float* g_x0  = A + o; o += (size_t)NB * 16 * 32768;   // skip, live until cat1
    float* g_c1  = A + o; o += (size_t)NB * 48 * 32768;   // concat1; later reused as d1b out
    float* g_p1  = A + o; o += (size_t)NB * 16 * 4096;
    float* g_t2  = A + o; o += (size_t)NB * 32 * 4096;    // e2a out; later reused as cat2 out
    float* g_x1  = A + o; o += (size_t)NB * 20 * 4096;    // skip, live until d2a
    float* g_p2  = A + o; o += (size_t)NB * 20 * 512;
    float* g_wx  = A + o; o += (size_t)NB * 30 * 512;
    float* g_h   = A + o; o += (size_t)NB * 10 * 512;
    float* g_c   = A + o; o += (size_t)NB * 10 * 512;
    float* g_hs  = A + o; o += (size_t)8  * 10 * 512;
    float* g_f   = A + o; o += (size_t)16 * 10 * 512;
    float* g_io  = A + o; o += (size_t)8  * 30 * 512;
    float* g_d2a = A + o; o += (size_t)NB * 20 * 4096;
    float* g_d2b = A + o; o += (size_t)NB * 32 * 4096;
    float* g_c2  = g_t2;   // t2 dead after e2b
    float* g_d1a = g_t1;   // t1 dead after e1b
    float* g_d1b = g_c1;   // c1 dead after d1a

    dim3 b32(8, 32), b16(4, 16), b8(2, 8);

    // ---- Encoder ----
    conv3_k<4><<<dim3(32, 4, NB), b32, 4 * 1  * 27 * sizeof(float)>>>(data, e1a_w, e1a_b, g_t1, 1, 16, 32, 1);
    conv3_k<4><<<dim3(32, 4, NB), b32, 4 * 16 * 27 * sizeof(float)>>>(g_t1, e1b_w, e1b_b, g_x0, 16, 16, 32, 1);
    { int tot = NB * 16 * 4096; pool_k<<<(tot + 255) / 256, 256>>>(g_x0, g_p1, 16, 16, tot); }
    conv3_k<4><<<dim3(16, 8, NB), b16, 4 * 16 * 27 * sizeof(float)>>>(g_p1, e2a_w, e2a_b, g_t2, 16, 32, 16, 1);
    conv3_k<4><<<dim3(16, 5, NB), b16, 4 * 32 * 27 * sizeof(float)>>>(g_t2, e2b_w, e2b_b, g_x1, 32, 20, 16, 1);
    { int tot = NB * 20 * 512; pool_k<<<(tot + 255) / 256, 256>>>(g_x1, g_p2, 20, 8, tot); }
    conv3_k<6><<<dim3(8, 5, NB), b8, 6 * 20 * 27 * sizeof(float)>>>(g_p2, w_iou, nullptr, g_wx, 20, 30, 8, 0);

    // ---- TreeLSTM: leaves, then internal levels bottom-up ----
    { int tot = 16 * 10 * 512; leaf_k<<<(tot + 255) / 256, 256>>>(g_wx, b_iou, c0, g_h, g_c); }
    for (int lvl = 3; lvl >= 0; lvl--){
        int base = (1 << lvl) - 1, P = 1 << lvl, cbase = 2 * base + 1;
        { int tot = P * 5120; hsum_k<<<(tot + 255) / 256, 256>>>(g_h, g_hs, cbase, P); }
        conv3_k<5><<<dim3(8, 2, 2 * P), b8, 5 * 10 * 27 * sizeof(float)>>>(
            g_h + (size_t)cbase * 5120, u_f, nullptr, g_f, 10, 10, 8, 0);
        conv3_k<6><<<dim3(8, 5, P), b8, 6 * 10 * 27 * sizeof(float)>>>(
            g_hs, u_iou, nullptr, g_io, 10, 30, 8, 0);
        { int tot = P * 5120; node_k<<<(tot + 255) / 256, 256>>>(g_io, g_f, b_iou, g_h, g_c, base, P, cbase); }
    }

    // ---- Decoder ----
    { int tot = NB * 30 * 4096; cat2_k<<<(tot + 255) / 256, 256>>>(g_h, g_x1, g_c2); }
    conv3_k<4><<<dim3(16, 5, NB), b16, 4 * 30 * 27 * sizeof(float)>>>(g_c2, d2a_w, d2a_b, g_d2a, 30, 20, 16, 1);
    conv3_k<4><<<dim3(16, 8, NB), b16, 4 * 20 * 27 * sizeof(float)>>>(g_d2a, d2b_w, d2b_b, g_d2b, 20, 32, 16, 1);
    { size_t tot = (size_t)NB * 48 * 32768;
      cat1_k<<<(unsigned)((tot + 255) / 256), 256>>>(g_d2b, g_x0, g_c1); }
    conv3_k<4><<<dim3(32, 4, NB), b32, 4 * 48 * 27 * sizeof(float)>>>(g_c1, d1a_w, d1a_b, g_d1a, 48, 16, 32, 1);
    conv3_k<4><<<dim3(32, 4, NB), b32, 4 * 16 * 27 * sizeof(float)>>>(g_d1a, d1b_w, d1b_b, g_d1b, 16, 16, 32, 1);
    { int tot = NB * 32768; d1c_k<<<(tot + 255) / 256, 256>>>(g_d1b, d1c_w, d1c_b, out); }
}

// round 6
// speedup vs baseline: 1.5071x; 1.5071x over previous
#include <cuda_runtime.h>

// ---------------------------------------------------------------------------
// TreeConvLSTM3d: 3D U-Net encoder -> conv TreeLSTM over 31-node binary tree
// -> 3D U-Net decoder with skip connections. All fp32 direct convolutions.
// R5: vectorized float4 + shfl-halo conv for D>=16 (L1-wavefront reduction).
// ---------------------------------------------------------------------------

#define NB 31

__device__ float g_arena[98000000];

__device__ __forceinline__ float sigm(float x){ return 1.f/(1.f + expf(-x)); }

// ---------------------------------------------------------------------------
// Vectorized 3x3x3 conv, pad=1. Each thread: 4-wide x strip (one float4 load),
// halo via warp shuffle from neighbor strips, COTILE output channels.
// Requires blockDim.x = D/4 >= 4 so shuffles stay in-warp per row.
// grid = (D, COUT/COTILE, NB), block = (D/4, D).
// ---------------------------------------------------------------------------
template<int COTILE>
__global__ void conv3v_k(const float* __restrict__ in, const float* __restrict__ w,
                         const float* __restrict__ bias, float* __restrict__ out,
                         int CIN, int COUT, int D, int doRelu)
{
    extern __shared__ float ws[];
    const int n   = blockIdx.z;
    const int co0 = blockIdx.y * COTILE;
    const int z   = blockIdx.x;
    const int tid = threadIdx.y * blockDim.x + threadIdx.x;
    const int nt  = blockDim.x * blockDim.y;
    const int wcount = COTILE * CIN * 27;
    const float* wsrc = w + (size_t)co0 * CIN * 27;
    for (int i = tid; i < wcount; i += nt) ws[i] = wsrc[i];
    __syncthreads();

    const int y  = threadIdx.y;
    const int x0 = threadIdx.x * 4;
    const bool hasL = threadIdx.x > 0;
    const bool hasR = threadIdx.x < blockDim.x - 1;
    const int DD = D * D;
    const size_t DDD = (size_t)DD * D;

    float acc[COTILE][4];
    #pragma unroll
    for (int t = 0; t < COTILE; t++){
        float bv = bias ? __ldg(bias + co0 + t) : 0.f;
        #pragma unroll
        for (int v = 0; v < 4; v++) acc[t][v] = bv;
    }

    for (int ci = 0; ci < CIN; ci++){
        const float* ipbase = in + ((size_t)n * CIN + ci) * DDD;
        const float* wci = ws + ci * 27;
        #pragma unroll
        for (int dz = 0; dz < 3; dz++){
            int zz = z + dz - 1;
            if ((unsigned)zz >= (unsigned)D) continue;      // uniform over block
            #pragma unroll
            for (int dy = 0; dy < 3; dy++){
                int yy = y + dy - 1;
                bool yok = (unsigned)yy < (unsigned)D;
                float4 rv;
                if (yok) rv = *(const float4*)(ipbase + (size_t)zz * DD + yy * D + x0);
                else     rv = make_float4(0.f, 0.f, 0.f, 0.f);
                // halo from neighbor strips (all lanes participate)
                float lft = __shfl_up_sync(0xffffffffu, rv.w, 1);
                float rgt = __shfl_down_sync(0xffffffffu, rv.x, 1);
                if (!hasL) lft = 0.f;
                if (!hasR) rgt = 0.f;
                float r[6] = {lft, rv.x, rv.y, rv.z, rv.w, rgt};
                const int tap0 = dz * 9 + dy * 3;
                #pragma unroll
                for (int dx = 0; dx < 3; dx++){
                    #pragma unroll
                    for (int t = 0; t < COTILE; t++){
                        float wv = wci[t * CIN * 27 + tap0 + dx];
                        #pragma unroll
                        for (int v = 0; v < 4; v++)
                            acc[t][v] += r[dx + v] * wv;
                    }
                }
            }
        }
    }

    #pragma unroll
    for (int t = 0; t < COTILE; t++){
        float* op = out + ((size_t)n * COUT + co0 + t) * DDD + (size_t)z * DD + y * D + x0;
        float4 rv;
        rv.x = acc[t][0]; rv.y = acc[t][1]; rv.z = acc[t][2]; rv.w = acc[t][3];
        if (doRelu){
            rv.x = fmaxf(rv.x, 0.f); rv.y = fmaxf(rv.y, 0.f);
            rv.z = fmaxf(rv.z, 0.f); rv.w = fmaxf(rv.w, 0.f);
        }
        *(float4*)op = rv;
    }
}

// Scalar conv path (kept for D=8 kernels; partial-warp blocks can't shfl-halo).
template<int COTILE>
__global__ void conv3_k(const float* __restrict__ in, const float* __restrict__ w,
                        const float* __restrict__ bias, float* __restrict__ out,
                        int CIN, int COUT, int D, int doRelu)
{
    extern __shared__ float ws[];
    const int n   = blockIdx.z;
    const int co0 = blockIdx.y * COTILE;
    const int z   = blockIdx.x;
    const int tid = threadIdx.y * blockDim.x + threadIdx.x;
    const int nt  = blockDim.x * blockDim.y;
    const int wcount = COTILE * CIN * 27;
    const float* wsrc = w + (size_t)co0 * CIN * 27;
    for (int i = tid; i < wcount; i += nt) ws[i] = wsrc[i];
    __syncthreads();

    const int y  = threadIdx.y;
    const int x0 = threadIdx.x * 4;
    const int DD = D * D;
    const size_t DDD = (size_t)DD * D;

    float acc[COTILE][4];
    #pragma unroll
    for (int t = 0; t < COTILE; t++){
        float bv = bias ? __ldg(bias + co0 + t) : 0.f;
        #pragma unroll
        for (int v = 0; v < 4; v++) acc[t][v] = bv;
    }

    for (int ci = 0; ci < CIN; ci++){
        const float* ipbase = in + ((size_t)n * CIN + ci) * DDD;
        const float* wci = ws + ci * 27;
        #pragma unroll
        for (int dz = 0; dz < 3; dz++){
            int zz = z + dz - 1;
            if ((unsigned)zz >= (unsigned)D) continue;
            #pragma unroll
            for (int dy = 0; dy < 3; dy++){
                int yy = y + dy - 1;
                bool yok = (unsigned)yy < (unsigned)D;
                const float* ip = ipbase + (size_t)zz * DD + yy * D;
                float r[6];
                #pragma unroll
                for (int j = 0; j < 6; j++){
                    int xx = x0 - 1 + j;
                    r[j] = (yok && (unsigned)xx < (unsigned)D) ? __ldg(ip + xx) : 0.f;
                }
                const int tap0 = dz * 9 + dy * 3;
                #pragma unroll
                for (int dx = 0; dx < 3; dx++){
                    #pragma unroll
                    for (int t = 0; t < COTILE; t++){
                        float wv = wci[t * CIN * 27 + tap0 + dx];
                        #pragma unroll
                        for (int v = 0; v < 4; v++)
                            acc[t][v] += r[dx + v] * wv;
                    }
                }
            }
        }
    }

    #pragma unroll
    for (int t = 0; t < COTILE; t++){
        float* op = out + ((size_t)n * COUT + co0 + t) * DDD + (size_t)z * DD + y * D + x0;
        #pragma unroll
        for (int v = 0; v < 4; v++){
            float r = acc[t][v];
            if (doRelu) r = fmaxf(r, 0.f);
            op[v] = r;
        }
    }
}

// 2x2x2 maxpool, stride 2.
__global__ void pool_k(const float* __restrict__ in, float* __restrict__ out,
                       int C, int Dout, int total)
{
    int idx = blockIdx.x * blockDim.x + threadIdx.x;
    if (idx >= total) return;
    int x = idx % Dout; int t = idx / Dout;
    int y = t % Dout; t /= Dout;
    int z = t % Dout; t /= Dout;
    int c = t % C; int n = t / C;
    int Din = Dout * 2;
    const float* p = in + ((((size_t)n * C + c) * Din + 2 * z) * Din + 2 * y) * Din + 2 * x;
    float m = fmaxf(fmaxf(p[0], p[1]), fmaxf(p[Din], p[Din + 1]));
    const float* q = p + (size_t)Din * Din;
    m = fmaxf(m, fmaxf(fmaxf(q[0], q[1]), fmaxf(q[Din], q[Din + 1])));
    out[idx] = m;
}

// Leaf nodes 15..30: iou = Wx, c_in = c0.
__global__ void leaf_k(const float* __restrict__ wx, const float* __restrict__ biou,
                       const float* __restrict__ c0, float* __restrict__ h, float* __restrict__ c)
{
    int idx = blockIdx.x * blockDim.x + threadIdx.x;
    if (idx >= 16 * 10 * 512) return;
    int vox = idx & 511;
    int ch  = (idx >> 9) % 10;
    int node = 15 + idx / 5120;
    float i = wx[((size_t)node * 30 + ch) * 512 + vox]      + biou[ch * 512 + vox];
    float o = wx[((size_t)node * 30 + 10 + ch) * 512 + vox] + biou[(10 + ch) * 512 + vox];
    float u = wx[((size_t)node * 30 + 20 + ch) * 512 + vox] + biou[(20 + ch) * 512 + vox];
    float cc = sigm(i) * tanhf(u) + c0[((size_t)node * 10 + ch) * 512 + vox];
    float hh = sigm(o) * tanhf(cc);
    h[((size_t)node * 10 + ch) * 512 + vox] = hh;
    c[((size_t)node * 10 + ch) * 512 + vox] = cc;
}

// h_sum over child pairs for a level.
__global__ void hsum_k(const float* __restrict__ h, float* __restrict__ hs, int cbase, int P)
{
    int idx = blockIdx.x * blockDim.x + threadIdx.x;
    if (idx >= P * 5120) return;
    int p = idx / 5120, r = idx % 5120;
    hs[idx] = h[(size_t)(cbase + 2 * p) * 5120 + r] + h[(size_t)(cbase + 2 * p + 1) * 5120 + r];
}

// Internal-node update.
__global__ void node_k(const float* __restrict__ iou, const float* __restrict__ fraw,
                       const float* __restrict__ biou,
                       float* __restrict__ h, float* __restrict__ c,
                       int base, int P, int cbase)
{
    int idx = blockIdx.x * blockDim.x + threadIdx.x;
    if (idx >= P * 5120) return;
    int vox = idx & 511;
    int ch  = (idx >> 9) % 10;
    int p   = idx / 5120;
    float i = iou[((size_t)p * 30 + ch) * 512 + vox]      + biou[ch * 512 + vox];
    float o = iou[((size_t)p * 30 + 10 + ch) * 512 + vox] + biou[(10 + ch) * 512 + vox];
    float u = iou[((size_t)p * 30 + 20 + ch) * 512 + vox] + biou[(20 + ch) * 512 + vox];
    float f0 = sigm(fraw[((size_t)(2 * p) * 10 + ch) * 512 + vox]);
    float f1 = sigm(fraw[((size_t)(2 * p + 1) * 10 + ch) * 512 + vox]);
    float cred = f0 * c[((size_t)(cbase + 2 * p) * 10 + ch) * 512 + vox]
               + f1 * c[((size_t)(cbase + 2 * p + 1) * 10 + ch) * 512 + vox];
    float cc = sigm(i) * tanhf(u) + cred;
    float hh = sigm(o) * tanhf(cc);
    h[((size_t)(base + p) * 10 + ch) * 512 + vox] = hh;
    c[((size_t)(base + p) * 10 + ch) * 512 + vox] = cc;
}

// concat(up2(h_all)[10ch], x1[20ch]) at 16^3.
__global__ void cat2_k(const float* __restrict__ h, const float* __restrict__ x1,
                       float* __restrict__ out)
{
    int idx = blockIdx.x * blockDim.x + threadIdx.x;
    if (idx >= NB * 30 * 4096) return;
    int vox = idx % 4096;
    int cch = (idx / 4096) % 30;
    int n   = idx / (30 * 4096);
    float v;
    if (cch < 10){
        int x = vox & 15, y = (vox >> 4) & 15, z = vox >> 8;
        v = h[((size_t)n * 10 + cch) * 512 + ((size_t)(z >> 1) * 8 + (y >> 1)) * 8 + (x >> 1)];
    } else {
        v = x1[((size_t)n * 20 + (cch - 10)) * 4096 + vox];
    }
    out[idx] = v;
}

// concat(up2(d2b)[32ch], x0[16ch]) at 32^3.
__global__ void cat1_k(const float* __restrict__ d2b, const float* __restrict__ x0,
                       float* __restrict__ out)
{
    size_t idx = (size_t)blockIdx.x * blockDim.x + threadIdx.x;
    if (idx >= (size_t)NB * 48 * 32768) return;
    int vox = (int)(idx & 32767);
    int cch = (int)((idx >> 15) % 48);
    int n   = (int)(idx / ((size_t)48 * 32768));
    float v;
    if (cch < 32){
        int x = vox & 31, y = (vox >> 5) & 31, z = vox >> 10;
        v = d2b[((size_t)n * 32 + cch) * 4096 + ((size_t)(z >> 1) * 16 + (y >> 1)) * 16 + (x >> 1)];
    } else {
        v = x0[((size_t)n * 16 + (cch - 32)) * 32768 + vox];
    }
    out[idx] = v;
}

// Final 1x1x1 conv: 16 -> 1.
__global__ void d1c_k(const float* __restrict__ in, const float* __restrict__ w,
                      const float* __restrict__ b, float* __restrict__ out)
{
    int idx = blockIdx.x * blockDim.x + threadIdx.x;
    if (idx >= NB * 32768) return;
    int n = idx >> 15;
    int vox = idx & 32767;
    float acc = __ldg(b);
    #pragma unroll
    for (int ci = 0; ci < 16; ci++)
        acc += in[((size_t)n * 16 + ci) * 32768 + vox] * __ldg(w + ci);
    out[idx] = acc;
}

extern "C" void kernel_launch(void* const* d_in, const int* in_sizes, int n_in,
                              void* d_out, int out_size)
{
    const float* data  = (const float*)d_in[0];
    const float* c0    = (const float*)d_in[2];
    const float* e1a_w = (const float*)d_in[3];  const float* e1a_b = (const float*)d_in[4];
    const float* e1b_w = (const float*)d_in[5];  const float* e1b_b = (const float*)d_in[6];
    const float* e2a_w = (const float*)d_in[7];  const float* e2a_b = (const float*)d_in[8];
    const float* e2b_w = (const float*)d_in[9];  const float* e2b_b = (const float*)d_in[10];
    const float* d2a_w = (const float*)d_in[11]; const float* d2a_b = (const float*)d_in[12];
    const float* d2b_w = (const float*)d_in[13]; const float* d2b_b = (const float*)d_in[14];
    const float* d1a_w = (const float*)d_in[15]; const float* d1a_b = (const float*)d_in[16];
    const float* d1b_w = (const float*)d_in[17]; const float* d1b_b = (const float*)d_in[18];
    const float* d1c_w = (const float*)d_in[19]; const float* d1c_b = (const float*)d_in[20];
    const float* w_iou = (const float*)d_in[21];
    const float* u_iou = (const float*)d_in[22];
    const float* u_f   = (const float*)d_in[23];
    const float* b_iou = (const float*)d_in[24];
    float* out = (float*)d_out;

    float* A = nullptr;
    cudaGetSymbolAddress((void**)&A, g_arena);

    size_t o = 0;
    float* g_t1  = A + o; o += (size_t)NB * 16 * 32768;   // e1a out; reused as d1a out
    float* g_x0  = A + o; o += (size_t)NB * 16 * 32768;   // skip, live until cat1
    float* g_c1  = A + o; o += (size_t)NB * 48 * 32768;   // concat1; reused as d1b out
    float* g_p1  = A + o; o += (size_t)NB * 16 * 4096;
    float* g_t2  = A + o; o += (size_t)NB * 32 * 4096;    // e2a out; reused as cat2 out
    float* g_x1  = A + o; o += (size_t)NB * 20 * 4096;
    float* g_p2  = A + o; o += (size_t)NB * 20 * 512;
    float* g_wx  = A + o; o += (size_t)NB * 30 * 512;
    float* g_h   = A + o; o += (size_t)NB * 10 * 512;
    float* g_c   = A + o; o += (size_t)NB * 10 * 512;
    float* g_hs  = A + o; o += (size_t)8  * 10 * 512;
    float* g_f   = A + o; o += (size_t)16 * 10 * 512;
    float* g_io  = A + o; o += (size_t)8  * 30 * 512;
    float* g_d2a = A + o; o += (size_t)NB * 20 * 4096;
    float* g_d2b = A + o; o += (size_t)NB * 32 * 4096;
    float* g_c2  = g_t2;
    float* g_d1a = g_t1;
    float* g_d1b = g_c1;

    dim3 b32(8, 32), b16(4, 16), b8(2, 8);
    const int WSZ = (int)sizeof(float) * 27;

    // ---- Encoder ----
    conv3v_k<8><<<dim3(32, 2, NB), b32, 8 * 1  * WSZ>>>(data, e1a_w, e1a_b, g_t1, 1, 16, 32, 1);
    conv3v_k<8><<<dim3(32, 2, NB), b32, 8 * 16 * WSZ>>>(g_t1, e1b_w, e1b_b, g_x0, 16, 16, 32, 1);
    { int tot = NB * 16 * 4096; pool_k<<<(tot + 255) / 256, 256>>>(g_x0, g_p1, 16, 16, tot); }
    conv3v_k<8><<<dim3(16, 4, NB), b16, 8 * 16 * WSZ>>>(g_p1, e2a_w, e2a_b, g_t2, 16, 32, 16, 1);
    conv3v_k<5><<<dim3(16, 4, NB), b16, 5 * 32 * WSZ>>>(g_t2, e2b_w, e2b_b, g_x1, 32, 20, 16, 1);
    { int tot = NB * 20 * 512; pool_k<<<(tot + 255) / 256, 256>>>(g_x1, g_p2, 20, 8, tot); }
    conv3_k<6><<<dim3(8, 5, NB), b8, 6 * 20 * WSZ>>>(g_p2, w_iou, nullptr, g_wx, 20, 30, 8, 0);

    // ---- TreeLSTM ----
    { int tot = 16 * 10 * 512; leaf_k<<<(tot + 255) / 256, 256>>>(g_wx, b_iou, c0, g_h, g_c); }
    for (int lvl = 3; lvl >= 0; lvl--){
        int base = (1 << lvl) - 1, P = 1 << lvl, cbase = 2 * base + 1;
        { int tot = P * 5120; hsum_k<<<(tot + 255) / 256, 256>>>(g_h, g_hs, cbase, P); }
        conv3_k<5><<<dim3(8, 2, 2 * P), b8, 5 * 10 * WSZ>>>(
            g_h + (size_t)cbase * 5120, u_f, nullptr, g_f, 10, 10, 8, 0);
        conv3_k<6><<<dim3(8, 5, P), b8, 6 * 10 * WSZ>>>(
            g_hs, u_iou, nullptr, g_io, 10, 30, 8, 0);
        { int tot = P * 5120; node_k<<<(tot + 255) / 256, 256>>>(g_io, g_f, b_iou, g_h, g_c, base, P, cbase); }
    }

    // ---- Decoder ----
    { int tot = NB * 30 * 4096; cat2_k<<<(tot + 255) / 256, 256>>>(g_h, g_x1, g_c2); }
    conv3v_k<5><<<dim3(16, 4, NB), b16, 5 * 30 * WSZ>>>(g_c2, d2a_w, d2a_b, g_d2a, 30, 20, 16, 1);
    conv3v_k<8><<<dim3(16, 4, NB), b16, 8 * 20 * WSZ>>>(g_d2a, d2b_w, d2b_b, g_d2b, 20, 32, 16, 1);
    { size_t tot = (size_t)NB * 48 * 32768;
      cat1_k<<<(unsigned)((tot + 255) / 256), 256>>>(g_d2b, g_x0, g_c1); }
    conv3v_k<8><<<dim3(32, 2, NB), b32, 8 * 48 * WSZ>>>(g_c1, d1a_w, d1a_b, g_d1a, 48, 16, 32, 1);
    conv3v_k<8><<<dim3(32, 2, NB), b32, 8 * 16 * WSZ>>>(g_d1a, d1b_w, d1b_b, g_d1b, 16, 16, 32, 1);
    { int tot = NB * 32768; d1c_k<<<(tot + 255) / 256, 256>>>(g_d1b, d1c_w, d1c_b, out); }
}